// round 17
// baseline (speedup 1.0000x reference)
#include <cuda_runtime.h>
#include <cuda_bf16.h>
#include <cstdint>

#define LQ 9216
#define C 768
#define NH 6
#define DH 128
#define NP 4
#define GRID 96
#define NOA 128   // padded offset+aw output width (48 offs + 24 logits + 56 pad)

// ---------------- scratch (no allocations allowed) ----------------
__device__ __nv_bfloat16 s_qn[LQ * C];
__device__ __nv_bfloat16 s_fn[LQ * C];
__device__ __nv_bfloat16 s_fn2[LQ * C];
__device__ __nv_bfloat16 s_samp[LQ * C];
__device__ __nv_bfloat16 s_val[LQ * C];
__device__ __nv_bfloat16 s_val2[LQ * C];
__device__ __nv_bfloat16 w_vp[2][C * C];
__device__ __nv_bfloat16 w_op[2][C * C];
__device__ __nv_bfloat16 w_oa[2][NOA * C];
__device__ float b_oa[2][NOA];
__device__ float g_q1[LQ * C];
__device__ float g_oa[LQ * NOA];

// ---------------- LayerNorm core ----------------
__device__ __forceinline__ void ln_row(const float* __restrict__ x,
                                       const float* __restrict__ w,
                                       const float* __restrict__ b,
                                       __nv_bfloat16* __restrict__ y, int row) {
    int t = threadIdx.x;
    int lane = t & 31, wid = t >> 5;
    float4 v = ((const float4*)(x + (size_t)row * C))[t];

    __shared__ float part[6];
    float s = v.x + v.y + v.z + v.w;
    #pragma unroll
    for (int o = 16; o; o >>= 1) s += __shfl_down_sync(0xffffffffu, s, o);
    if (!lane) part[wid] = s;
    __syncthreads();
    float mu = (part[0] + part[1] + part[2] + part[3] + part[4] + part[5]) * (1.f / C);

    float dx = v.x - mu, dy = v.y - mu, dz = v.z - mu, dw = v.w - mu;
    s = dx * dx + dy * dy + dz * dz + dw * dw;
    __syncthreads();
    #pragma unroll
    for (int o = 16; o; o >>= 1) s += __shfl_down_sync(0xffffffffu, s, o);
    if (!lane) part[wid] = s;
    __syncthreads();
    float rs = rsqrtf((part[0] + part[1] + part[2] + part[3] + part[4] + part[5]) * (1.f / C) + 1e-6f);

    float4 wv = ((const float4*)w)[t];
    float4 bv = ((const float4*)b)[t];
    __nv_bfloat162 p0 = __floats2bfloat162_rn(dx * rs * wv.x + bv.x, dy * rs * wv.y + bv.y);
    __nv_bfloat162 p1 = __floats2bfloat162_rn(dz * rs * wv.z + bv.z, dw * rs * wv.w + bv.w);
    __nv_bfloat162* yr = (__nv_bfloat162*)(y + (size_t)row * C);
    yr[t * 2] = p0;
    yr[t * 2 + 1] = p1;
}

// ---------------- prelude: 3x LN + all weight prep in ONE launch -------------
__global__ __launch_bounds__(192) void prelude(
    const float* __restrict__ x0, const float* __restrict__ w0,
    const float* __restrict__ b0, __nv_bfloat16* __restrict__ y0,
    const float* __restrict__ x1, const float* __restrict__ w1,
    const float* __restrict__ b1, __nv_bfloat16* __restrict__ y1,
    const float* __restrict__ x2, const float* __restrict__ w2,
    const float* __restrict__ b2, __nv_bfloat16* __restrict__ y2,
    const float* __restrict__ vp1, const float* __restrict__ op1,
    const float* __restrict__ vp2, const float* __restrict__ op2,
    const float* __restrict__ so1, const float* __restrict__ aw1,
    const float* __restrict__ so1b, const float* __restrict__ aw1b,
    const float* __restrict__ so2, const float* __restrict__ aw2,
    const float* __restrict__ so2b, const float* __restrict__ aw2b,
    __nv_bfloat16* __restrict__ wvp, __nv_bfloat16* __restrict__ wop,
    __nv_bfloat16* __restrict__ woa, float* __restrict__ boa) {
    int row = blockIdx.x;
    if (row < LQ) { ln_row(x0, w0, b0, y0, row); return; }
    if (row < 2 * LQ) { ln_row(x1, w1, b1, y1, row - LQ); return; }
    if (row < 3 * LQ) { ln_row(x2, w2, b2, y2, row - 2 * LQ); return; }

    const int nW = C * C;   // 589824 = 3072 * 192
    int i = (row - 3 * LQ) * 192 + threadIdx.x;
    if (i < nW) {
        wvp[i] = __float2bfloat16(vp1[i]);
        wop[i] = __float2bfloat16(op1[i]);
        wvp[nW + i] = __float2bfloat16(vp2[i]);
        wop[nW + i] = __float2bfloat16(op2[i]);
    }
    if (i < NOA * C) {
        float v1 = 0.f, v2 = 0.f;
        if (i < 48 * C) { v1 = so1[i]; v2 = so2[i]; }
        else if (i < 72 * C) { v1 = aw1[i - 48 * C]; v2 = aw2[i - 48 * C]; }
        woa[i] = __float2bfloat16(v1);
        woa[NOA * C + i] = __float2bfloat16(v2);
    }
    if (i < NOA) {
        boa[i]       = (i < 48) ? so1b[i] : (i < 72 ? aw1b[i - 48] : 0.f);
        boa[NOA + i] = (i < 48) ? so2b[i] : (i < 72 ? aw2b[i - 48] : 0.f);
    }
}

__global__ __launch_bounds__(192) void ln_one(const float* __restrict__ x,
                                              const float* __restrict__ w,
                                              const float* __restrict__ b,
                                              __nv_bfloat16* __restrict__ y) {
    ln_row(x, w, b, y, blockIdx.x);
}

// ---------------- bf16 HMMA GEMM core, 64xNTx64, 3-stage cp.async ------------
#define MT 64
#define GBN 128
#define GBK 64
#define LDA 72   // elements; 144B row stride (16B aligned, staggers banks)
#define NSTG 3
#define SMEM_GEMM (NSTG * (MT + GBN) * LDA * 2)   // 82944 B

__device__ __forceinline__ void mma16816(float* c, const uint32_t* a, const uint32_t* b) {
    asm volatile(
        "mma.sync.aligned.m16n8k16.row.col.f32.bf16.bf16.f32 "
        "{%0,%1,%2,%3}, {%4,%5,%6,%7}, {%8,%9}, {%0,%1,%2,%3};\n"
        : "+f"(c[0]), "+f"(c[1]), "+f"(c[2]), "+f"(c[3])
        : "r"(a[0]), "r"(a[1]), "r"(a[2]), "r"(a[3]), "r"(b[0]), "r"(b[1]));
}

__device__ __forceinline__ void cp16(uint32_t s, const void* g) {
    asm volatile("cp.async.cg.shared.global [%0], [%1], 16;\n" :: "r"(s), "l"(g));
}

// MODE 0: out = acc + bias ; MODE 1: out = resid + gamma*(acc+bias)
// NT: n-tile width (128 or 64)
template <int MODE, bool OUT_BF16, int NT>
__device__ __forceinline__ void gemm_core(const __nv_bfloat16* __restrict__ A,
                                          const __nv_bfloat16* __restrict__ B,
                                          const float* __restrict__ bias,
                                          const float* __restrict__ resid,
                                          const float* __restrict__ gamma,
                                          void* __restrict__ Cout,
                                          int N, int K, int bm, int bn,
                                          __nv_bfloat16* smem) {
    const uint32_t STGB = (MT + NT) * LDA * 2;    // bytes per stage
    const uint32_t BOFF = MT * LDA * 2;           // B offset within a stage
    constexpr int NPR = NT / 32;                  // x4-ldmatrix loads for B
    constexpr int NA = NT / 16;                   // n8 MMA tiles per warp
    constexpr int KS = GBK / 16;                  // 4 k-steps per chunk

    int tid = threadIdx.x;
    int warp = tid >> 5, lane = tid & 31;
    int wm = (warp >> 1) * 16;                     // 4 warps along m (16 rows each)
    int wn = (warp & 1) * (NT / 2);                // 2 warps along n

    uint32_t sBase = (uint32_t)__cvta_generic_to_shared(smem);

    uint32_t a_addr[KS], b_addr[NPR][KS];
    #pragma unroll
    for (int ks = 0; ks < KS; ks++)
        a_addr[ks] = sBase +
            ((wm + (lane & 15)) * LDA + ks * 16 + (lane >> 4) * 8) * 2;
    #pragma unroll
    for (int pr = 0; pr < NPR; pr++)
        #pragma unroll
        for (int ks = 0; ks < KS; ks++)
            b_addr[pr][ks] = sBase + BOFF +
                ((wn + pr * 16 + (lane & 15)) * LDA + ks * 16 + (lane >> 4) * 8) * 2;

    const __nv_bfloat16* Abase = A + (size_t)bm * K;
    const __nv_bfloat16* Bbase = B + (size_t)bn * K;

    auto load_stage = [&](int stage, int k0) {
        uint32_t so = sBase + stage * STGB;
        // A: MT rows * 8 chunks of 16B (GBK=64 elems = 128B/row)
        #pragma unroll
        for (int i = 0; i < MT * 8; i += 256) {
            int idx = i + tid;
            int r = idx >> 3, c = (idx & 7) * 8;
            cp16(so + r * (LDA * 2) + c * 2, Abase + (size_t)r * K + k0 + c);
        }
        // B: NT rows * 8 chunks
        #pragma unroll
        for (int i = 0; i < NT * 8; i += 256) {
            int idx = i + tid;
            int r = idx >> 3, c = (idx & 7) * 8;
            cp16(so + BOFF + r * (LDA * 2) + c * 2, Bbase + (size_t)r * K + k0 + c);
        }
        asm volatile("cp.async.commit_group;\n");
    };

    float acc[NA][4] = {};

    const int NK = K / GBK;   // 12
    load_stage(0, 0);
    load_stage(1, GBK);

    for (int it = 0; it < NK; it++) {
        if (it + 1 < NK)
            asm volatile("cp.async.wait_group 1;\n");
        else
            asm volatile("cp.async.wait_group 0;\n");
        __syncthreads();

        if (it + 2 < NK) load_stage((it + 2) % NSTG, (it + 2) * GBK);

        uint32_t soff = (it % NSTG) * STGB;
        #pragma unroll
        for (int ks = 0; ks < KS; ks++) {
            uint32_t af[4], bf[NA][2];
            asm volatile("ldmatrix.sync.aligned.m8n8.x4.shared.b16 {%0,%1,%2,%3}, [%4];"
                         : "=r"(af[0]), "=r"(af[1]), "=r"(af[2]), "=r"(af[3])
                         : "r"(a_addr[ks] + soff));
            #pragma unroll
            for (int pr = 0; pr < NPR; pr++) {
                uint32_t r0, r1, r2, r3;
                asm volatile("ldmatrix.sync.aligned.m8n8.x4.shared.b16 {%0,%1,%2,%3}, [%4];"
                             : "=r"(r0), "=r"(r1), "=r"(r2), "=r"(r3)
                             : "r"(b_addr[pr][ks] + soff));
                bf[pr * 2 + 0][0] = r0; bf[pr * 2 + 0][1] = r2;
                bf[pr * 2 + 1][0] = r1; bf[pr * 2 + 1][1] = r3;
            }
            #pragma unroll
            for (int na = 0; na < NA; na++)
                mma16816(acc[na], af, bf[na]);
        }
    }

    int tr = lane >> 2, tc = (lane & 3) * 2;
    #pragma unroll
    for (int half = 0; half < 2; half++) {
        int m = bm + wm + half * 8 + tr;
        #pragma unroll
        for (int na = 0; na < NA; na++) {
            int n = bn + wn + na * 8 + tc;
            float v0 = acc[na][half * 2 + 0] + bias[n];
            float v1 = acc[na][half * 2 + 1] + bias[n + 1];
            if (MODE == 1) {
                v0 = resid[(size_t)m * N + n] + gamma[n] * v0;
                v1 = resid[(size_t)m * N + n + 1] + gamma[n + 1] * v1;
            }
            if (OUT_BF16)
                *(__nv_bfloat162*)((__nv_bfloat16*)Cout + (size_t)m * N + n) =
                    __floats2bfloat162_rn(v0, v1);
            else
                *(float2*)((float*)Cout + (size_t)m * N + n) = make_float2(v0, v1);
        }
    }
}

// Fused: value-GEMM1 (bx 0..5), value-GEMM2 (bx 6..11), oa-GEMM1 (bx 12..13, NT=64)
__global__ __launch_bounds__(256, 2) void gemm_fused3(
    const __nv_bfloat16* __restrict__ A0, const __nv_bfloat16* __restrict__ B0,
    const float* __restrict__ bias0, __nv_bfloat16* __restrict__ out0,
    const __nv_bfloat16* __restrict__ A1, const __nv_bfloat16* __restrict__ B1,
    const float* __restrict__ bias1, __nv_bfloat16* __restrict__ out1,
    const __nv_bfloat16* __restrict__ A2, const __nv_bfloat16* __restrict__ B2,
    const float* __restrict__ bias2, float* __restrict__ out2) {
    extern __shared__ __nv_bfloat16 smem[];
    int bx = blockIdx.x, bm = blockIdx.y * MT;
    if (bx < 6)
        gemm_core<0, true, 128>(A0, B0, bias0, nullptr, nullptr, out0, C, C, bm, bx * GBN, smem);
    else if (bx < 12)
        gemm_core<0, true, 128>(A1, B1, bias1, nullptr, nullptr, out1, C, C, bm, (bx - 6) * GBN, smem);
    else
        gemm_core<0, false, 64>(A2, B2, bias2, nullptr, nullptr, out2, NOA, C, bm, (bx - 12) * 64, smem);
}

// Standalone out-GEMMs (NT=128) and oa-GEMM2 (NT=64)
template <int MODE, bool OUT_BF16>
__global__ __launch_bounds__(256, 2) void gemm_bf16(const __nv_bfloat16* __restrict__ A,
                                                    const __nv_bfloat16* __restrict__ B,
                                                    const float* __restrict__ bias,
                                                    const float* __restrict__ resid,
                                                    const float* __restrict__ gamma,
                                                    void* __restrict__ Cout,
                                                    int N, int K) {
    extern __shared__ __nv_bfloat16 smem[];
    gemm_core<MODE, OUT_BF16, 128>(A, B, bias, resid, gamma, Cout, N, K,
                                   blockIdx.y * MT, blockIdx.x * GBN, smem);
}

__global__ __launch_bounds__(256, 2) void gemm_oa(const __nv_bfloat16* __restrict__ A,
                                                  const __nv_bfloat16* __restrict__ B,
                                                  const float* __restrict__ bias,
                                                  float* __restrict__ Cout) {
    extern __shared__ __nv_bfloat16 smem[];
    gemm_core<0, false, 64>(A, B, bias, nullptr, nullptr, Cout, NOA, C,
                            blockIdx.y * MT, blockIdx.x * 64, smem);
}

// ---------------- bilinear sampling: uint4 gathers, 2-point load batching ----
__device__ __forceinline__ void accum8(float* acc, float w, const uint4& r) {
    const uint32_t rr[4] = {r.x, r.y, r.z, r.w};
    #pragma unroll
    for (int c = 0; c < 4; c++) {
        __nv_bfloat162 b = *(const __nv_bfloat162*)&rr[c];
        acc[c * 2 + 0] = fmaf(w, __bfloat162float(b.x), acc[c * 2 + 0]);
        acc[c * 2 + 1] = fmaf(w, __bfloat162float(b.y), acc[c * 2 + 1]);
    }
}

__global__ __launch_bounds__(384) void sampler_kernel(const uint4* __restrict__ val,
                                                      const float* __restrict__ ref,
                                                      const float* __restrict__ oa,
                                                      uint4* __restrict__ out) {
    int q0 = blockIdx.x * 4;
    int tid = threadIdx.x;
    __shared__ float s[4][72];
    __shared__ float pw[96][4];
    __shared__ int   po[96][4];
    if (tid < 288) s[tid / 72][tid % 72] = oa[(size_t)(q0 + tid / 72) * NOA + tid % 72];
    __syncthreads();

    if (tid < 96) {
        int lq = tid / 24, hp = tid % 24;
        int h = hp >> 2, p = hp & 3;
        const float* sq = s[lq];
        int q = q0 + lq;

        float lg0 = sq[48 + h * 4 + 0], lg1 = sq[48 + h * 4 + 1];
        float lg2 = sq[48 + h * 4 + 2], lg3 = sq[48 + h * 4 + 3];
        float mx = fmaxf(fmaxf(lg0, lg1), fmaxf(lg2, lg3));
        float se = __expf(lg0 - mx) + __expf(lg1 - mx) + __expf(lg2 - mx) + __expf(lg3 - mx);
        float wp = __expf(sq[48 + h * 4 + p] - mx) / se;

        float px = ref[q * 2]     * (float)GRID + sq[(h * 4 + p) * 2]     - 0.5f;
        float py = ref[q * 2 + 1] * (float)GRID + sq[(h * 4 + p) * 2 + 1] - 0.5f;
        float fx0 = floorf(px), fy0 = floorf(py);
        int x0 = (int)fx0, y0 = (int)fy0;
        float fx = px - fx0, fy = py - fy0;

        float vx0 = ((unsigned)x0 < (unsigned)GRID) ? 1.f : 0.f;
        float vx1 = ((unsigned)(x0 + 1) < (unsigned)GRID) ? 1.f : 0.f;
        float vy0 = ((unsigned)y0 < (unsigned)GRID) ? 1.f : 0.f;
        float vy1 = ((unsigned)(y0 + 1) < (unsigned)GRID) ? 1.f : 0.f;
        pw[tid][0] = wp * (1.f - fy) * (1.f - fx) * vy0 * vx0;
        pw[tid][1] = wp * (1.f - fy) * fx         * vy0 * vx1;
        pw[tid][2] = wp * fy         * (1.f - fx) * vy1 * vx0;
        pw[tid][3] = wp * fy         * fx         * vy1 * vx1;

        int x0c = min(GRID - 1, max(0, x0)), x1c = min(GRID - 1, max(0, x0 + 1));
        int y0c = min(GRID - 1, max(0, y0)), y1c = min(GRID - 1, max(0, y0 + 1));
        po[tid][0] = (y0c * GRID + x0c) * (C / 8);
        po[tid][1] = (y0c * GRID + x1c) * (C / 8);
        po[tid][2] = (y1c * GRID + x0c) * (C / 8);
        po[tid][3] = (y1c * GRID + x1c) * (C / 8);
    }
    __syncthreads();

    int lq = tid / 96;
    int t = tid % 96;
    int h = t >> 4;
    int q = q0 + lq;
    int base = lq * 24 + h * 4;

    float acc[8] = {};
    #pragma unroll
    for (int pp = 0; pp < 2; pp++) {
        float4 wA = *(const float4*)pw[base + 2 * pp + 0];
        float4 wB = *(const float4*)pw[base + 2 * pp + 1];
        int4 oA = *(const int4*)po[base + 2 * pp + 0];
        int4 oB = *(const int4*)po[base + 2 * pp + 1];
        uint4 rA0 = __ldg(&val[oA.x + t]);
        uint4 rA1 = __ldg(&val[oA.y + t]);
        uint4 rA2 = __ldg(&val[oA.z + t]);
        uint4 rA3 = __ldg(&val[oA.w + t]);
        uint4 rB0 = __ldg(&val[oB.x + t]);
        uint4 rB1 = __ldg(&val[oB.y + t]);
        uint4 rB2 = __ldg(&val[oB.z + t]);
        uint4 rB3 = __ldg(&val[oB.w + t]);
        accum8(acc, wA.x, rA0);
        accum8(acc, wA.y, rA1);
        accum8(acc, wA.z, rA2);
        accum8(acc, wA.w, rA3);
        accum8(acc, wB.x, rB0);
        accum8(acc, wB.y, rB1);
        accum8(acc, wB.z, rB2);
        accum8(acc, wB.w, rB3);
    }
    uint4 packed;
    __nv_bfloat162 p0 = __floats2bfloat162_rn(acc[0], acc[1]);
    __nv_bfloat162 p1 = __floats2bfloat162_rn(acc[2], acc[3]);
    __nv_bfloat162 p2 = __floats2bfloat162_rn(acc[4], acc[5]);
    __nv_bfloat162 p3 = __floats2bfloat162_rn(acc[6], acc[7]);
    packed.x = *(uint32_t*)&p0;
    packed.y = *(uint32_t*)&p1;
    packed.z = *(uint32_t*)&p2;
    packed.w = *(uint32_t*)&p3;
    out[(size_t)q * (C / 8) + t] = packed;
}

// ---------------- host side ----------------
extern "C" void kernel_launch(void* const* d_in, const int* in_sizes, int n_in,
                              void* d_out, int out_size) {
    const float* query = (const float*)d_in[0];
    const float* ref   = (const float*)d_in[1];
    const float* feat  = (const float*)d_in[2];
    const float* feat2 = (const float*)d_in[3];
    const float* qn_w = (const float*)d_in[6];
    const float* qn_b = (const float*)d_in[7];
    const float* fn_w = (const float*)d_in[8];
    const float* fn_b = (const float*)d_in[9];
    const float* so_w = (const float*)d_in[10];
    const float* so_b = (const float*)d_in[11];
    const float* aw_w = (const float*)d_in[12];
    const float* aw_b = (const float*)d_in[13];
    const float* vp_w = (const float*)d_in[14];
    const float* vp_b = (const float*)d_in[15];
    const float* op_w = (const float*)d_in[16];
    const float* op_b = (const float*)d_in[17];
    const float* gamma = (const float*)d_in[18];
    const float* qn2_w = (const float*)d_in[19];
    const float* qn2_b = (const float*)d_in[20];
    const float* fn2_w = (const float*)d_in[21];
    const float* fn2_b = (const float*)d_in[22];
    const float* so2_w = (const float*)d_in[23];
    const float* so2_b = (const float*)d_in[24];
    const float* aw2_w = (const float*)d_in[25];
    const float* aw2_b = (const float*)d_in[26];
    const float* vp2_w = (const float*)d_in[27];
    const float* vp2_b = (const float*)d_in[28];
    const float* op2_w = (const float*)d_in[29];
    const float* op2_b = (const float*)d_in[30];
    const float* gamma2 = (const float*)d_in[31];
    float* out = (float*)d_out;

    __nv_bfloat16 *p_qn, *p_fn, *p_fn2, *p_samp, *p_val, *p_val2, *pw_vp, *pw_op, *pw_oa;
    float *p_q1, *p_oa, *pb_oa;
    cudaGetSymbolAddress((void**)&p_qn, s_qn);
    cudaGetSymbolAddress((void**)&p_fn, s_fn);
    cudaGetSymbolAddress((void**)&p_fn2, s_fn2);
    cudaGetSymbolAddress((void**)&p_samp, s_samp);
    cudaGetSymbolAddress((void**)&p_val, s_val);
    cudaGetSymbolAddress((void**)&p_val2, s_val2);
    cudaGetSymbolAddress((void**)&pw_vp, w_vp);
    cudaGetSymbolAddress((void**)&pw_op, w_op);
    cudaGetSymbolAddress((void**)&pw_oa, w_oa);
    cudaGetSymbolAddress((void**)&pb_oa, b_oa);
    cudaGetSymbolAddress((void**)&p_q1, g_q1);
    cudaGetSymbolAddress((void**)&p_oa, g_oa);

    static bool attr_done = false;
    if (!attr_done) {
        cudaFuncSetAttribute(gemm_fused3,
                             cudaFuncAttributeMaxDynamicSharedMemorySize, SMEM_GEMM);
        cudaFuncSetAttribute(gemm_bf16<1, false>,
                             cudaFuncAttributeMaxDynamicSharedMemorySize, SMEM_GEMM);
        cudaFuncSetAttribute(gemm_oa,
                             cudaFuncAttributeMaxDynamicSharedMemorySize, SMEM_GEMM);
        attr_done = true;
    }

    // Prelude: LN(query), LN(feat), LN(feat2) + all weight conversion, 1 launch
    prelude<<<3 * LQ + 3072, 192>>>(query, qn_w, qn_b, p_qn,
                                    feat, fn_w, fn_b, p_fn,
                                    feat2, fn2_w, fn2_b, p_fn2,
                                    vp_w, op_w, vp2_w, op2_w,
                                    so_w, aw_w, so_b, aw_b,
                                    so2_w, aw2_w, so2_b, aw2_b,
                                    pw_vp, pw_op, pw_oa, pb_oa);

    const int nW = C * C;
    // Fused: value-GEMM1, value-GEMM2 (stage-2 hoisted), oa-GEMM1 (2 n-tiles)
    gemm_fused3<<<dim3(14, LQ / MT), 256, SMEM_GEMM>>>(
        p_fn, pw_vp, vp_b, p_val,
        p_fn2, pw_vp + nW, vp2_b, p_val2,
        p_qn, pw_oa, pb_oa, p_oa);

    // Stage 1 tail
    sampler_kernel<<<LQ / 4, 384>>>((const uint4*)p_val, ref, p_oa, (uint4*)p_samp);
    gemm_bf16<1, false><<<dim3(C / GBN, LQ / MT), 256, SMEM_GEMM>>>(
        p_samp, pw_op, op_b, query, gamma, p_q1, C, C);

    // Stage 2 (val2 already computed)
    ln_one<<<LQ, 192>>>(p_q1, qn2_w, qn2_b, p_qn);
    gemm_oa<<<dim3(2, LQ / MT), 256, SMEM_GEMM>>>(
        p_qn, pw_oa + NOA * C, pb_oa + NOA, p_oa);
    sampler_kernel<<<LQ / 4, 384>>>((const uint4*)p_val2, ref, p_oa, (uint4*)p_samp);
    gemm_bf16<1, false><<<dim3(C / GBN, LQ / MT), 256, SMEM_GEMM>>>(
        p_samp, pw_op + nW, op2_b, p_q1, gamma2, out, C, C);
}